// round 6
// baseline (speedup 1.0000x reference)
#include <cuda_runtime.h>
#include <cstdint>

#define BH 64
#define SS 8192
#define DD 64
#define SPLIT 16

__device__ float g_kv_part[SPLIT][BH][DD*DD];
__device__ float g_ks_part[SPLIT][BH][DD];
__device__ float g_bT[BH][DD][DD];   // g_bT[e][d] = tf32(kv[d][e])
__device__ float g_ks2[BH][DD];      // ksum

__device__ __forceinline__ float to_tf32f(float f){
    uint32_t u; asm("cvt.rna.tf32.f32 %0, %1;" : "=r"(u) : "f"(f));
    return __uint_as_float(u);
}
__device__ __forceinline__ uint32_t cvt_tf32(float f){
    uint32_t u; asm("cvt.rna.tf32.f32 %0, %1;" : "=r"(u) : "f"(f));
    return u;
}
__device__ __forceinline__ uint32_t relu_tf32(float f){
    uint32_t u; float r = fmaxf(f, 0.f);
    asm("cvt.rna.tf32.f32 %0, %1;" : "=r"(u) : "f"(r));
    return u;
}
__device__ __forceinline__ void mma_tf32(float c[4], uint32_t a0, uint32_t a1,
                                         uint32_t a2, uint32_t a3,
                                         uint32_t b0, uint32_t b1){
    asm volatile(
        "mma.sync.aligned.m16n8k8.row.col.f32.tf32.tf32.f32 "
        "{%0,%1,%2,%3}, {%4,%5,%6,%7}, {%8,%9}, {%0,%1,%2,%3};"
        : "+f"(c[0]), "+f"(c[1]), "+f"(c[2]), "+f"(c[3])
        : "r"(a0), "r"(a1), "r"(a2), "r"(a3), "r"(b0), "r"(b1));
}

// ---------------------------------------------------------------------------
// Pass 1 (tf32 mma.sync): kv_part[d][e] = sum_s relu(k[s][d])*v[s][e]
// 4 warps/block, 4 blocks/bh (grid 256, 2 blocks/SM); warp owns 512 s-rows.
// ---------------------------------------------------------------------------
#define P1_BLOCKS 4
#define S_PER_WARP 512
#define KSTEPS (S_PER_WARP/8)   // 64

__global__ void __launch_bounds__(128, 2) pass1_kernel(const float* __restrict__ K,
                                                       const float* __restrict__ V){
    const int bh = blockIdx.y;
    const int tid = threadIdx.x;
    const int w = tid >> 5, lane = tid & 31;
    const int g = lane >> 2, tg = lane & 3;
    const int sp = blockIdx.x * 4 + w;           // 0..15 split index

    const float* Kp = K + ((size_t)bh*SS + (size_t)sp*S_PER_WARP)*DD;
    const float* Vp = V + ((size_t)bh*SS + (size_t)sp*S_PER_WARP)*DD;

    float C[4][8][4];
    #pragma unroll
    for(int mt=0;mt<4;mt++)
        #pragma unroll
        for(int nt=0;nt<8;nt++){ C[mt][nt][0]=0.f; C[mt][nt][1]=0.f; C[mt][nt][2]=0.f; C[mt][nt][3]=0.f; }
    float ksum[4][2];
    #pragma unroll
    for(int mt=0;mt<4;mt++){ ksum[mt][0]=0.f; ksum[mt][1]=0.f; }

    float ra[16], rb[16], ra2[16], rb2[16];

    #pragma unroll
    for(int mt=0;mt<4;mt++){
        int d0 = mt*16 + g;
        ra[mt*4+0] = Kp[(size_t)tg*DD + d0];
        ra[mt*4+1] = Kp[(size_t)tg*DD + d0 + 8];
        ra[mt*4+2] = Kp[(size_t)(tg+4)*DD + d0];
        ra[mt*4+3] = Kp[(size_t)(tg+4)*DD + d0 + 8];
    }
    #pragma unroll
    for(int nt=0;nt<8;nt++){
        rb[nt*2+0] = Vp[(size_t)tg*DD + nt*8 + g];
        rb[nt*2+1] = Vp[(size_t)(tg+4)*DD + nt*8 + g];
    }

    for(int ks=0; ks<KSTEPS; ks++){
        if(ks+1 < KSTEPS){
            const float* kb = Kp + (size_t)(ks+1)*8*DD;
            const float* vb = Vp + (size_t)(ks+1)*8*DD;
            #pragma unroll
            for(int mt=0;mt<4;mt++){
                int d0 = mt*16 + g;
                ra2[mt*4+0] = kb[(size_t)tg*DD + d0];
                ra2[mt*4+1] = kb[(size_t)tg*DD + d0 + 8];
                ra2[mt*4+2] = kb[(size_t)(tg+4)*DD + d0];
                ra2[mt*4+3] = kb[(size_t)(tg+4)*DD + d0 + 8];
            }
            #pragma unroll
            for(int nt=0;nt<8;nt++){
                rb2[nt*2+0] = vb[(size_t)tg*DD + nt*8 + g];
                rb2[nt*2+1] = vb[(size_t)(tg+4)*DD + nt*8 + g];
            }
        }
        uint32_t A[4][4], B[8][2];
        #pragma unroll
        for(int mt=0;mt<4;mt++){
            A[mt][0] = relu_tf32(ra[mt*4+0]);
            A[mt][1] = relu_tf32(ra[mt*4+1]);
            A[mt][2] = relu_tf32(ra[mt*4+2]);
            A[mt][3] = relu_tf32(ra[mt*4+3]);
            ksum[mt][0] += __uint_as_float(A[mt][0]) + __uint_as_float(A[mt][2]);
            ksum[mt][1] += __uint_as_float(A[mt][1]) + __uint_as_float(A[mt][3]);
        }
        #pragma unroll
        for(int nt=0;nt<8;nt++){
            B[nt][0] = cvt_tf32(rb[nt*2+0]);
            B[nt][1] = cvt_tf32(rb[nt*2+1]);
        }
        #pragma unroll
        for(int mt=0;mt<4;mt++)
            #pragma unroll
            for(int nt=0;nt<8;nt++)
                mma_tf32(C[mt][nt], A[mt][0], A[mt][1], A[mt][2], A[mt][3],
                         B[nt][0], B[nt][1]);
        #pragma unroll
        for(int i=0;i<16;i++){ ra[i]=ra2[i]; rb[i]=rb2[i]; }
    }

    float* outp = g_kv_part[sp][bh];
    #pragma unroll
    for(int mt=0;mt<4;mt++){
        int r0 = mt*16 + g, r1 = r0 + 8;
        #pragma unroll
        for(int nt=0;nt<8;nt++){
            int col = nt*8 + tg*2;
            *(float2*)(outp + (size_t)r0*DD + col) = make_float2(C[mt][nt][0], C[mt][nt][1]);
            *(float2*)(outp + (size_t)r1*DD + col) = make_float2(C[mt][nt][2], C[mt][nt][3]);
        }
    }
    #pragma unroll
    for(int mt=0;mt<4;mt++){
        #pragma unroll
        for(int r=0;r<2;r++){
            float s = ksum[mt][r];
            s += __shfl_xor_sync(0xffffffffu, s, 1);
            s += __shfl_xor_sync(0xffffffffu, s, 2);
            ksum[mt][r] = s;
        }
    }
    if(tg == 0){
        #pragma unroll
        for(int mt=0;mt<4;mt++){
            g_ks_part[sp][bh][mt*16 + g]     = ksum[mt][0];
            g_ks_part[sp][bh][mt*16 + g + 8] = ksum[mt][1];
        }
    }
}

// ---------------------------------------------------------------------------
// Reduce: sum partials -> g_bT[bh][e][d] = tf32(kv[d][e]), g_ks2 = ksum
// ---------------------------------------------------------------------------
__global__ void __launch_bounds__(256) reduce_kernel(){
    int bh = blockIdx.x;
    int tid = threadIdx.x;
    #pragma unroll
    for(int i=0;i<4;i++){
        int idx = tid + i*256;
        int d = idx >> 4;
        int e = (idx & 15) * 4;
        float4 s = make_float4(0.f,0.f,0.f,0.f);
        #pragma unroll
        for(int c=0;c<SPLIT;c++){
            float4 p = ((const float4*)g_kv_part[c][bh])[idx];
            s.x+=p.x; s.y+=p.y; s.z+=p.z; s.w+=p.w;
        }
        g_bT[bh][e+0][d] = to_tf32f(s.x);
        g_bT[bh][e+1][d] = to_tf32f(s.y);
        g_bT[bh][e+2][d] = to_tf32f(s.z);
        g_bT[bh][e+3][d] = to_tf32f(s.w);
    }
    if(tid < DD){
        float s=0.f;
        #pragma unroll
        for(int c=0;c<SPLIT;c++) s += g_ks_part[c][bh][tid];
        g_ks2[bh][tid] = s;
    }
}

// ---------------------------------------------------------------------------
// Pass 2 (tf32 mma.sync): out[s][e] = (phi_q @ kv)[s][e] / max(phi_q·ksum,1e-6)
// 4 warps/block, 4 blocks/bh (grid 256, 2 blocks/SM); warp owns 512 rows.
// ---------------------------------------------------------------------------
#define P2_PARTS 4
#define ROWS_PER_WARP (SS / P2_PARTS / 4)     // 512
#define MT_PER_WARP (ROWS_PER_WARP / 16)      // 32

__global__ void __launch_bounds__(128, 2) pass2_kernel(const float* __restrict__ Q,
                                                       float* __restrict__ O){
    const int bh = blockIdx.y;
    const int part = blockIdx.x;
    const int tid = threadIdx.x;
    const int w = tid >> 5, lane = tid & 31;
    const int g = lane >> 2, tg = lane & 3;

    uint32_t B0[8][8], B1[8][8];
    {
        const float* Bp = &g_bT[bh][0][0];
        #pragma unroll
        for(int n=0;n<8;n++){
            #pragma unroll
            for(int s=0;s<8;s++){
                B0[n][s] = __float_as_uint(Bp[(n*8+g)*DD + s*8+tg]);
                B1[n][s] = __float_as_uint(Bp[(n*8+g)*DD + s*8+tg+4]);
            }
        }
    }
    float ksA[8], ksB[8];
    #pragma unroll
    for(int s=0;s<8;s++){
        ksA[s] = g_ks2[bh][s*8+tg];
        ksB[s] = g_ks2[bh][s*8+tg+4];
    }

    const size_t rowbase = (size_t)bh*SS + (size_t)part*(SS/P2_PARTS) + (size_t)w*ROWS_PER_WARP;

    for(int mt=0; mt<MT_PER_WARP; mt++){
        const float* Ap = Q + (rowbase + (size_t)mt*16)*DD;
        // front-batched raw loads (MLP)
        float raw[32];
        #pragma unroll
        for(int s=0;s<8;s++){
            raw[s*4+0] = Ap[(size_t)g*DD      + s*8+tg];
            raw[s*4+1] = Ap[(size_t)(g+8)*DD  + s*8+tg];
            raw[s*4+2] = Ap[(size_t)g*DD      + s*8+tg+4];
            raw[s*4+3] = Ap[(size_t)(g+8)*DD  + s*8+tg+4];
        }
        float C[8][4];
        #pragma unroll
        for(int n=0;n<8;n++){ C[n][0]=0.f; C[n][1]=0.f; C[n][2]=0.f; C[n][3]=0.f; }
        float n0 = 0.f, n1 = 0.f;

        #pragma unroll
        for(int s=0;s<8;s++){
            uint32_t a0 = relu_tf32(raw[s*4+0]);
            uint32_t a1 = relu_tf32(raw[s*4+1]);
            uint32_t a2 = relu_tf32(raw[s*4+2]);
            uint32_t a3 = relu_tf32(raw[s*4+3]);
            n0 += __uint_as_float(a0)*ksA[s] + __uint_as_float(a2)*ksB[s];
            n1 += __uint_as_float(a1)*ksA[s] + __uint_as_float(a3)*ksB[s];
            #pragma unroll
            for(int n=0;n<8;n++)
                mma_tf32(C[n], a0, a1, a2, a3, B0[n][s], B1[n][s]);
        }

        n0 += __shfl_xor_sync(0xffffffffu, n0, 1);
        n0 += __shfl_xor_sync(0xffffffffu, n0, 2);
        n1 += __shfl_xor_sync(0xffffffffu, n1, 1);
        n1 += __shfl_xor_sync(0xffffffffu, n1, 2);
        float i0 = 1.0f / fmaxf(n0, 1e-6f);
        float i1 = 1.0f / fmaxf(n1, 1e-6f);

        float* Or0 = O + (rowbase + (size_t)mt*16 + g)*DD;
        float* Or1 = Or0 + 8*DD;
        #pragma unroll
        for(int n=0;n<8;n++){
            float2 v0 = make_float2(C[n][0]*i0, C[n][1]*i0);
            float2 v1 = make_float2(C[n][2]*i1, C[n][3]*i1);
            *(float2*)(Or0 + n*8 + tg*2) = v0;
            *(float2*)(Or1 + n*8 + tg*2) = v1;
        }
    }
}

extern "C" void kernel_launch(void* const* d_in, const int* in_sizes, int n_in,
                              void* d_out, int out_size){
    const float* Q = (const float*)d_in[0];
    const float* K = (const float*)d_in[1];
    const float* V = (const float*)d_in[2];
    float* O = (float*)d_out;
    pass1_kernel<<<dim3(P1_BLOCKS, BH), 128>>>(K, V);
    reduce_kernel<<<BH, 256>>>();
    pass2_kernel<<<dim3(P2_PARTS, BH), 128>>>(Q, O);
}

// round 8
// speedup vs baseline: 1.2728x; 1.2728x over previous
#include <cuda_runtime.h>
#include <cstdint>

#define BH 64
#define SS 8192
#define DD 64
#define SPLIT 16
#define S_PER_WARP 512
#define KSTEPS (S_PER_WARP/8)   // 64

// pass1 smem: per warp 4 K-slots + 4 V-slots of [8][72] floats
#define P1_RS 72
#define P1_SLOT (8*P1_RS)               // 576 floats
#define P1_WARPF (8*P1_SLOT)            // 4608 floats (4 K + 4 V slots)
#define P1_SMEM (8*P1_WARPF*4)          // 147456 bytes

// pass2 smem: per warp 4 Q-slots of [16][68] floats
#define P2_RS 68
#define P2_SLOT (16*P2_RS)              // 1088 floats
#define P2_WARPF (4*P2_SLOT)            // 4352 floats
#define P2_SMEM (8*P2_WARPF*4)          // 139264 bytes

__device__ float g_kv_part[SPLIT][BH][DD*DD];
__device__ float g_ks_part[SPLIT][BH][DD];
__device__ float g_bT[BH][DD][DD];   // g_bT[e][d] = tf32(kv[d][e])
__device__ float g_ks2[BH][DD];      // ksum

__device__ __forceinline__ float to_tf32f(float f){
    uint32_t u; asm("cvt.rna.tf32.f32 %0, %1;" : "=r"(u) : "f"(f));
    return __uint_as_float(u);
}
__device__ __forceinline__ uint32_t cvt_tf32(float f){
    uint32_t u; asm("cvt.rna.tf32.f32 %0, %1;" : "=r"(u) : "f"(f));
    return u;
}
__device__ __forceinline__ uint32_t relu_tf32(float f){
    uint32_t u; float r = fmaxf(f, 0.f);
    asm("cvt.rna.tf32.f32 %0, %1;" : "=r"(u) : "f"(r));
    return u;
}
__device__ __forceinline__ void mma_tf32(float c[4], uint32_t a0, uint32_t a1,
                                         uint32_t a2, uint32_t a3,
                                         uint32_t b0, uint32_t b1){
    asm volatile(
        "mma.sync.aligned.m16n8k8.row.col.f32.tf32.tf32.f32 "
        "{%0,%1,%2,%3}, {%4,%5,%6,%7}, {%8,%9}, {%0,%1,%2,%3};"
        : "+f"(c[0]), "+f"(c[1]), "+f"(c[2]), "+f"(c[3])
        : "r"(a0), "r"(a1), "r"(a2), "r"(a3), "r"(b0), "r"(b1));
}
__device__ __forceinline__ unsigned smem_u32(const void* p){
    return (unsigned)__cvta_generic_to_shared(p);
}
#define CP_ASYNC16(dst,src) asm volatile("cp.async.ca.shared.global [%0],[%1],16;\n"::"r"(dst),"l"(src))
#define CP_COMMIT()  asm volatile("cp.async.commit_group;\n")
#define CP_WAIT(n)   asm volatile("cp.async.wait_group %0;\n"::"n"(n))

// ---------------------------------------------------------------------------
// Pass 1: kv_part[d][e] = sum_s relu(k[s][d])*v[s][e]; 8 warps/block,
// warp-private cp.async ring (4 slots, 2 ahead), conflict-free LDS (pad 72).
// ---------------------------------------------------------------------------
__global__ void __launch_bounds__(256, 1) pass1_kernel(const float* __restrict__ K,
                                                       const float* __restrict__ V){
    extern __shared__ float dsm[];
    const int bh = blockIdx.y;
    const int tid = threadIdx.x;
    const int w = tid >> 5, lane = tid & 31;
    const int g = lane >> 2, tg = lane & 3;
    const int sp = blockIdx.x * 8 + w;           // 0..15 split

    const float* Kp = K + ((size_t)bh*SS + (size_t)sp*S_PER_WARP)*DD;
    const float* Vp = V + ((size_t)bh*SS + (size_t)sp*S_PER_WARP)*DD;
    float* wbase = dsm + w*P1_WARPF;

    // stage mapping: lane -> row (lane>>2); 4 chunks/lane cover all 64 cols
    const int sr = lane >> 2;
    const int sc0 = (lane & 3) * 4;   // + 16*j, j=0..3

    float C[4][8][4];
    #pragma unroll
    for(int mt=0;mt<4;mt++)
        #pragma unroll
        for(int nt=0;nt<8;nt++){ C[mt][nt][0]=0.f; C[mt][nt][1]=0.f; C[mt][nt][2]=0.f; C[mt][nt][3]=0.f; }
    float ksum[4][2];
    #pragma unroll
    for(int mt=0;mt<4;mt++){ ksum[mt][0]=0.f; ksum[mt][1]=0.f; }

    #define P1_ISSUE(t) do { \
        int slot = (t) & 3; \
        float* dk = wbase + slot*P1_SLOT + sr*P1_RS + sc0; \
        float* dv = dk + 4*P1_SLOT; \
        const float* sk = Kp + ((size_t)(t)*8 + sr)*DD + sc0; \
        const float* sv = Vp + ((size_t)(t)*8 + sr)*DD + sc0; \
        _Pragma("unroll") \
        for(int j=0;j<4;j++){ \
            CP_ASYNC16(smem_u32(dk + 16*j), sk + 16*j); \
            CP_ASYNC16(smem_u32(dv + 16*j), sv + 16*j); \
        } \
    } while(0)

    P1_ISSUE(0); CP_COMMIT();
    P1_ISSUE(1); CP_COMMIT();

    for(int ks=0; ks<KSTEPS; ks++){
        if(ks+2 < KSTEPS) P1_ISSUE(ks+2);
        CP_COMMIT();
        CP_WAIT(2);
        __syncwarp();
        const float* skb = wbase + (ks&3)*P1_SLOT;
        const float* svb = wbase + 4*P1_SLOT + (ks&3)*P1_SLOT;

        uint32_t A[4][4], B[8][2];
        #pragma unroll
        for(int mt=0;mt<4;mt++){
            int d0 = mt*16 + g;
            A[mt][0] = relu_tf32(skb[tg*P1_RS + d0]);
            A[mt][1] = relu_tf32(skb[tg*P1_RS + d0 + 8]);
            A[mt][2] = relu_tf32(skb[(tg+4)*P1_RS + d0]);
            A[mt][3] = relu_tf32(skb[(tg+4)*P1_RS + d0 + 8]);
            ksum[mt][0] += __uint_as_float(A[mt][0]) + __uint_as_float(A[mt][2]);
            ksum[mt][1] += __uint_as_float(A[mt][1]) + __uint_as_float(A[mt][3]);
        }
        #pragma unroll
        for(int nt=0;nt<8;nt++){
            B[nt][0] = cvt_tf32(svb[tg*P1_RS + nt*8 + g]);
            B[nt][1] = cvt_tf32(svb[(tg+4)*P1_RS + nt*8 + g]);
        }
        #pragma unroll
        for(int mt=0;mt<4;mt++)
            #pragma unroll
            for(int nt=0;nt<8;nt++)
                mma_tf32(C[mt][nt], A[mt][0], A[mt][1], A[mt][2], A[mt][3],
                         B[nt][0], B[nt][1]);
        __syncwarp();
    }
    #undef P1_ISSUE

    float* outp = g_kv_part[sp][bh];
    #pragma unroll
    for(int mt=0;mt<4;mt++){
        int r0 = mt*16 + g, r1 = r0 + 8;
        #pragma unroll
        for(int nt=0;nt<8;nt++){
            int col = nt*8 + tg*2;
            *(float2*)(outp + (size_t)r0*DD + col) = make_float2(C[mt][nt][0], C[mt][nt][1]);
            *(float2*)(outp + (size_t)r1*DD + col) = make_float2(C[mt][nt][2], C[mt][nt][3]);
        }
    }
    #pragma unroll
    for(int mt=0;mt<4;mt++){
        #pragma unroll
        for(int r=0;r<2;r++){
            float s = ksum[mt][r];
            s += __shfl_xor_sync(0xffffffffu, s, 1);
            s += __shfl_xor_sync(0xffffffffu, s, 2);
            ksum[mt][r] = s;
        }
    }
    if(tg == 0){
        #pragma unroll
        for(int mt=0;mt<4;mt++){
            g_ks_part[sp][bh][mt*16 + g]     = ksum[mt][0];
            g_ks_part[sp][bh][mt*16 + g + 8] = ksum[mt][1];
        }
    }
}

// ---------------------------------------------------------------------------
// Reduce: sum partials -> g_bT[bh][e][d] = tf32(kv[d][e]), g_ks2 = ksum
// ---------------------------------------------------------------------------
__global__ void __launch_bounds__(256) reduce_kernel(){
    int bh = blockIdx.x;
    int tid = threadIdx.x;
    #pragma unroll
    for(int i=0;i<4;i++){
        int idx = tid + i*256;
        int d = idx >> 4;
        int e = (idx & 15) * 4;
        float4 s = make_float4(0.f,0.f,0.f,0.f);
        #pragma unroll
        for(int c=0;c<SPLIT;c++){
            float4 p = ((const float4*)g_kv_part[c][bh])[idx];
            s.x+=p.x; s.y+=p.y; s.z+=p.z; s.w+=p.w;
        }
        g_bT[bh][e+0][d] = to_tf32f(s.x);
        g_bT[bh][e+1][d] = to_tf32f(s.y);
        g_bT[bh][e+2][d] = to_tf32f(s.z);
        g_bT[bh][e+3][d] = to_tf32f(s.w);
    }
    if(tid < DD){
        float s=0.f;
        #pragma unroll
        for(int c=0;c<SPLIT;c++) s += g_ks_part[c][bh][tid];
        g_ks2[bh][tid] = s;
    }
}

// ---------------------------------------------------------------------------
// Pass 2: out[s][e] = (phi_q @ kv)[s][e] / max(phi_q·ksum,1e-6)
// 8 warps/block, warp = 512 rows; Q staged via warp-private cp.async ring.
// ---------------------------------------------------------------------------
#define P2_PARTS 2
#define MT_PER_WARP 32

__global__ void __launch_bounds__(256, 1) pass2_kernel(const float* __restrict__ Q,
                                                       float* __restrict__ O){
    extern __shared__ float dsm[];
    const int bh = blockIdx.y;
    const int part = blockIdx.x;
    const int tid = threadIdx.x;
    const int w = tid >> 5, lane = tid & 31;
    const int g = lane >> 2, tg = lane & 3;
    float* qs = dsm + w*P2_WARPF;

    uint32_t B0[8][8], B1[8][8];
    {
        const float* Bp = &g_bT[bh][0][0];
        #pragma unroll
        for(int n=0;n<8;n++){
            #pragma unroll
            for(int s=0;s<8;s++){
                B0[n][s] = __float_as_uint(Bp[(n*8+g)*DD + s*8+tg]);
                B1[n][s] = __float_as_uint(Bp[(n*8+g)*DD + s*8+tg+4]);
            }
        }
    }
    float ksA[8], ksB[8];
    #pragma unroll
    for(int s=0;s<8;s++){
        ksA[s] = g_ks2[bh][s*8+tg];
        ksB[s] = g_ks2[bh][s*8+tg+4];
    }

    const size_t rowbase = (size_t)bh*SS + (size_t)part*(SS/P2_PARTS) + (size_t)w*512;
    const float* Qp = Q + rowbase*DD;

    // slot: 16 rows x 64 cols = 256 chunks of 16B; 8 chunks/lane
    #define P2_ISSUE(t) do { \
        int slot = (t) & 3; \
        _Pragma("unroll") \
        for(int j=0;j<8;j++){ \
            int ch = lane + j*32; \
            int r = ch >> 4, c = (ch & 15) * 4; \
            unsigned dq = smem_u32(qs + slot*P2_SLOT + r*P2_RS + c); \
            CP_ASYNC16(dq, Qp + ((size_t)(t)*16 + r)*DD + c); \
        } \
    } while(0)

    P2_ISSUE(0); CP_COMMIT();
    P2_ISSUE(1); CP_COMMIT();

    for(int mt=0; mt<MT_PER_WARP; mt++){
        if(mt+2 < MT_PER_WARP) P2_ISSUE(mt+2);
        CP_COMMIT();
        CP_WAIT(2);
        __syncwarp();
        const float* sq = qs + (mt&3)*P2_SLOT;

        float C[8][4];
        #pragma unroll
        for(int n=0;n<8;n++){ C[n][0]=0.f; C[n][1]=0.f; C[n][2]=0.f; C[n][3]=0.f; }
        float n0 = 0.f, n1 = 0.f;

        #pragma unroll
        for(int s=0;s<8;s++){
            uint32_t a0 = relu_tf32(sq[g*P2_RS     + s*8+tg]);
            uint32_t a1 = relu_tf32(sq[(g+8)*P2_RS + s*8+tg]);
            uint32_t a2 = relu_tf32(sq[g*P2_RS     + s*8+tg+4]);
            uint32_t a3 = relu_tf32(sq[(g+8)*P2_RS + s*8+tg+4]);
            n0 += __uint_as_float(a0)*ksA[s] + __uint_as_float(a2)*ksB[s];
            n1 += __uint_as_float(a1)*ksA[s] + __uint_as_float(a3)*ksB[s];
            #pragma unroll
            for(int n=0;n<8;n++)
                mma_tf32(C[n], a0, a1, a2, a3, B0[n][s], B1[n][s]);
        }

        n0 += __shfl_xor_sync(0xffffffffu, n0, 1);
        n0 += __shfl_xor_sync(0xffffffffu, n0, 2);
        n1 += __shfl_xor_sync(0xffffffffu, n1, 1);
        n1 += __shfl_xor_sync(0xffffffffu, n1, 2);
        float i0 = 1.0f / fmaxf(n0, 1e-6f);
        float i1 = 1.0f / fmaxf(n1, 1e-6f);

        float* Or0 = O + (rowbase + (size_t)mt*16 + g)*DD;
        float* Or1 = Or0 + 8*DD;
        #pragma unroll
        for(int n=0;n<8;n++){
            float2 v0 = make_float2(C[n][0]*i0, C[n][1]*i0);
            float2 v1 = make_float2(C[n][2]*i1, C[n][3]*i1);
            *(float2*)(Or0 + n*8 + tg*2) = v0;
            *(float2*)(Or1 + n*8 + tg*2) = v1;
        }
        __syncwarp();
    }
    #undef P2_ISSUE
}

extern "C" void kernel_launch(void* const* d_in, const int* in_sizes, int n_in,
                              void* d_out, int out_size){
    const float* Q = (const float*)d_in[0];
    const float* K = (const float*)d_in[1];
    const float* V = (const float*)d_in[2];
    float* O = (float*)d_out;
    cudaFuncSetAttribute(pass1_kernel, cudaFuncAttributeMaxDynamicSharedMemorySize, P1_SMEM);
    cudaFuncSetAttribute(pass2_kernel, cudaFuncAttributeMaxDynamicSharedMemorySize, P2_SMEM);
    pass1_kernel<<<dim3(2, BH), 256, P1_SMEM>>>(K, V);
    reduce_kernel<<<BH, 256>>>();
    pass2_kernel<<<dim3(P2_PARTS, BH), 256, P2_SMEM>>>(Q, O);
}

// round 9
// speedup vs baseline: 1.3102x; 1.0293x over previous
#include <cuda_runtime.h>
#include <cstdint>

#define BH 64
#define SS 8192
#define DD 64
#define SPLIT 16
#define S_PER_WARP 512
#define KSTEPS (S_PER_WARP/8)   // 64

// pass1 smem: per warp 4 K-slots + 4 V-slots of [8][72] floats
#define P1_RS 72
#define P1_SLOT (8*P1_RS)               // 576 floats
#define P1_WARPF (8*P1_SLOT)            // 4608 floats (4 K + 4 V slots)
#define P1_WARPS 4
#define P1_SMEM (P1_WARPS*P1_WARPF*4)   // 73728 bytes

// pass2 smem: per warp 4 Q-slots of [16][68] floats
#define P2_RS 68
#define P2_SLOT (16*P2_RS)              // 1088 floats
#define P2_WARPF (4*P2_SLOT)            // 4352 floats
#define P2_WARPS 4
#define P2_SMEM (P2_WARPS*P2_WARPF*4)   // 69632 bytes

__device__ float g_kv_part[SPLIT][BH][DD*DD];
__device__ float g_ks_part[SPLIT][BH][DD];
__device__ float g_bT[BH][DD][DD];   // g_bT[e][d] = tf32(kv[d][e])
__device__ float g_ks2[BH][DD];      // ksum

__device__ __forceinline__ float to_tf32f(float f){
    uint32_t u; asm("cvt.rna.tf32.f32 %0, %1;" : "=r"(u) : "f"(f));
    return __uint_as_float(u);
}
__device__ __forceinline__ uint32_t cvt_tf32(float f){
    uint32_t u; asm("cvt.rna.tf32.f32 %0, %1;" : "=r"(u) : "f"(f));
    return u;
}
__device__ __forceinline__ uint32_t relu_tf32(float f){
    uint32_t u; float r = fmaxf(f, 0.f);
    asm("cvt.rna.tf32.f32 %0, %1;" : "=r"(u) : "f"(r));
    return u;
}
__device__ __forceinline__ void mma_tf32(float c[4], uint32_t a0, uint32_t a1,
                                         uint32_t a2, uint32_t a3,
                                         uint32_t b0, uint32_t b1){
    asm volatile(
        "mma.sync.aligned.m16n8k8.row.col.f32.tf32.tf32.f32 "
        "{%0,%1,%2,%3}, {%4,%5,%6,%7}, {%8,%9}, {%0,%1,%2,%3};"
        : "+f"(c[0]), "+f"(c[1]), "+f"(c[2]), "+f"(c[3])
        : "r"(a0), "r"(a1), "r"(a2), "r"(a3), "r"(b0), "r"(b1));
}
__device__ __forceinline__ unsigned smem_u32(const void* p){
    return (unsigned)__cvta_generic_to_shared(p);
}
#define CP_ASYNC16(dst,src) asm volatile("cp.async.ca.shared.global [%0],[%1],16;\n"::"r"(dst),"l"(src))
#define CP_COMMIT()  asm volatile("cp.async.commit_group;\n")
#define CP_WAIT(n)   asm volatile("cp.async.wait_group %0;\n"::"n"(n))

// ---------------------------------------------------------------------------
// Pass 1: kv_part[d][e] = sum_s relu(k[s][d])*v[s][e]; 4 warps/block,
// grid 4x64=256 blocks (2/SM), warp-private cp.async ring (4 slots, 2 ahead).
// ---------------------------------------------------------------------------
__global__ void __launch_bounds__(128, 2) pass1_kernel(const float* __restrict__ K,
                                                       const float* __restrict__ V){
    extern __shared__ float dsm[];
    const int bh = blockIdx.y;
    const int tid = threadIdx.x;
    const int w = tid >> 5, lane = tid & 31;
    const int g = lane >> 2, tg = lane & 3;
    const int sp = blockIdx.x * P1_WARPS + w;    // 0..15 split

    const float* Kp = K + ((size_t)bh*SS + (size_t)sp*S_PER_WARP)*DD;
    const float* Vp = V + ((size_t)bh*SS + (size_t)sp*S_PER_WARP)*DD;
    float* wbase = dsm + w*P1_WARPF;

    const int sr = lane >> 2;
    const int sc0 = (lane & 3) * 4;   // + 16*j, j=0..3

    float C[4][8][4];
    #pragma unroll
    for(int mt=0;mt<4;mt++)
        #pragma unroll
        for(int nt=0;nt<8;nt++){ C[mt][nt][0]=0.f; C[mt][nt][1]=0.f; C[mt][nt][2]=0.f; C[mt][nt][3]=0.f; }
    float ksum[4][2];
    #pragma unroll
    for(int mt=0;mt<4;mt++){ ksum[mt][0]=0.f; ksum[mt][1]=0.f; }

    #define P1_ISSUE(t) do { \
        int slot = (t) & 3; \
        float* dk = wbase + slot*P1_SLOT + sr*P1_RS + sc0; \
        float* dv = dk + 4*P1_SLOT; \
        const float* sk = Kp + ((size_t)(t)*8 + sr)*DD + sc0; \
        const float* sv = Vp + ((size_t)(t)*8 + sr)*DD + sc0; \
        _Pragma("unroll") \
        for(int j=0;j<4;j++){ \
            CP_ASYNC16(smem_u32(dk + 16*j), sk + 16*j); \
            CP_ASYNC16(smem_u32(dv + 16*j), sv + 16*j); \
        } \
    } while(0)

    P1_ISSUE(0); CP_COMMIT();
    P1_ISSUE(1); CP_COMMIT();

    for(int ks=0; ks<KSTEPS; ks++){
        if(ks+2 < KSTEPS) P1_ISSUE(ks+2);
        CP_COMMIT();
        CP_WAIT(2);
        __syncwarp();
        const float* skb = wbase + (ks&3)*P1_SLOT;
        const float* svb = wbase + 4*P1_SLOT + (ks&3)*P1_SLOT;

        uint32_t A[4][4], B[8][2];
        #pragma unroll
        for(int mt=0;mt<4;mt++){
            int d0 = mt*16 + g;
            A[mt][0] = relu_tf32(skb[tg*P1_RS + d0]);
            A[mt][1] = relu_tf32(skb[tg*P1_RS + d0 + 8]);
            A[mt][2] = relu_tf32(skb[(tg+4)*P1_RS + d0]);
            A[mt][3] = relu_tf32(skb[(tg+4)*P1_RS + d0 + 8]);
            ksum[mt][0] += __uint_as_float(A[mt][0]) + __uint_as_float(A[mt][2]);
            ksum[mt][1] += __uint_as_float(A[mt][1]) + __uint_as_float(A[mt][3]);
        }
        #pragma unroll
        for(int nt=0;nt<8;nt++){
            B[nt][0] = cvt_tf32(svb[tg*P1_RS + nt*8 + g]);
            B[nt][1] = cvt_tf32(svb[(tg+4)*P1_RS + nt*8 + g]);
        }
        #pragma unroll
        for(int mt=0;mt<4;mt++)
            #pragma unroll
            for(int nt=0;nt<8;nt++)
                mma_tf32(C[mt][nt], A[mt][0], A[mt][1], A[mt][2], A[mt][3],
                         B[nt][0], B[nt][1]);
        __syncwarp();
    }
    #undef P1_ISSUE

    float* outp = g_kv_part[sp][bh];
    #pragma unroll
    for(int mt=0;mt<4;mt++){
        int r0 = mt*16 + g, r1 = r0 + 8;
        #pragma unroll
        for(int nt=0;nt<8;nt++){
            int col = nt*8 + tg*2;
            *(float2*)(outp + (size_t)r0*DD + col) = make_float2(C[mt][nt][0], C[mt][nt][1]);
            *(float2*)(outp + (size_t)r1*DD + col) = make_float2(C[mt][nt][2], C[mt][nt][3]);
        }
    }
    #pragma unroll
    for(int mt=0;mt<4;mt++){
        #pragma unroll
        for(int r=0;r<2;r++){
            float s = ksum[mt][r];
            s += __shfl_xor_sync(0xffffffffu, s, 1);
            s += __shfl_xor_sync(0xffffffffu, s, 2);
            ksum[mt][r] = s;
        }
    }
    if(tg == 0){
        #pragma unroll
        for(int mt=0;mt<4;mt++){
            g_ks_part[sp][bh][mt*16 + g]     = ksum[mt][0];
            g_ks_part[sp][bh][mt*16 + g + 8] = ksum[mt][1];
        }
    }
}

// ---------------------------------------------------------------------------
// Reduce: sum partials -> g_bT[bh][e][d] = tf32(kv[d][e]), g_ks2 = ksum
// ---------------------------------------------------------------------------
__global__ void __launch_bounds__(256) reduce_kernel(){
    int bh = blockIdx.x;
    int tid = threadIdx.x;
    #pragma unroll
    for(int i=0;i<4;i++){
        int idx = tid + i*256;
        int d = idx >> 4;
        int e = (idx & 15) * 4;
        float4 s = make_float4(0.f,0.f,0.f,0.f);
        #pragma unroll
        for(int c=0;c<SPLIT;c++){
            float4 p = ((const float4*)g_kv_part[c][bh])[idx];
            s.x+=p.x; s.y+=p.y; s.z+=p.z; s.w+=p.w;
        }
        g_bT[bh][e+0][d] = to_tf32f(s.x);
        g_bT[bh][e+1][d] = to_tf32f(s.y);
        g_bT[bh][e+2][d] = to_tf32f(s.z);
        g_bT[bh][e+3][d] = to_tf32f(s.w);
    }
    if(tid < DD){
        float s=0.f;
        #pragma unroll
        for(int c=0;c<SPLIT;c++) s += g_ks_part[c][bh][tid];
        g_ks2[bh][tid] = s;
    }
}

// ---------------------------------------------------------------------------
// Pass 2: out[s][e] = (phi_q @ kv)[s][e] / max(phi_q·ksum,1e-6)
// 4 warps/block, grid 4x64=256 (2/SM); Q staged via warp-private ring.
// ---------------------------------------------------------------------------
#define P2_PARTS 4
#define MT_PER_WARP (SS / P2_PARTS / P2_WARPS / 16)   // 32

__global__ void __launch_bounds__(128, 2) pass2_kernel(const float* __restrict__ Q,
                                                       float* __restrict__ O){
    extern __shared__ float dsm[];
    const int bh = blockIdx.y;
    const int part = blockIdx.x;
    const int tid = threadIdx.x;
    const int w = tid >> 5, lane = tid & 31;
    const int g = lane >> 2, tg = lane & 3;
    float* qs = dsm + w*P2_WARPF;

    uint32_t B0[8][8], B1[8][8];
    {
        const float* Bp = &g_bT[bh][0][0];
        #pragma unroll
        for(int n=0;n<8;n++){
            #pragma unroll
            for(int s=0;s<8;s++){
                B0[n][s] = __float_as_uint(Bp[(n*8+g)*DD + s*8+tg]);
                B1[n][s] = __float_as_uint(Bp[(n*8+g)*DD + s*8+tg+4]);
            }
        }
    }
    float ksA[8], ksB[8];
    #pragma unroll
    for(int s=0;s<8;s++){
        ksA[s] = g_ks2[bh][s*8+tg];
        ksB[s] = g_ks2[bh][s*8+tg+4];
    }

    const size_t rowbase = (size_t)bh*SS + (size_t)part*(SS/P2_PARTS)
                         + (size_t)w*(MT_PER_WARP*16);
    const float* Qp = Q + rowbase*DD;

    #define P2_ISSUE(t) do { \
        int slot = (t) & 3; \
        _Pragma("unroll") \
        for(int j=0;j<8;j++){ \
            int ch = lane + j*32; \
            int r = ch >> 4, c = (ch & 15) * 4; \
            unsigned dq = smem_u32(qs + slot*P2_SLOT + r*P2_RS + c); \
            CP_ASYNC16(dq, Qp + ((size_t)(t)*16 + r)*DD + c); \
        } \
    } while(0)

    P2_ISSUE(0); CP_COMMIT();
    P2_ISSUE(1); CP_COMMIT();

    for(int mt=0; mt<MT_PER_WARP; mt++){
        if(mt+2 < MT_PER_WARP) P2_ISSUE(mt+2);
        CP_COMMIT();
        CP_WAIT(2);
        __syncwarp();
        const float* sq = qs + (mt&3)*P2_SLOT;

        float C[8][4];
        #pragma unroll
        for(int n=0;n<8;n++){ C[n][0]=0.f; C[n][1]=0.f; C[n][2]=0.f; C[n][3]=0.f; }
        float n0 = 0.f, n1 = 0.f;

        #pragma unroll
        for(int s=0;s<8;s++){
            uint32_t a0 = relu_tf32(sq[g*P2_RS     + s*8+tg]);
            uint32_t a1 = relu_tf32(sq[(g+8)*P2_RS + s*8+tg]);
            uint32_t a2 = relu_tf32(sq[g*P2_RS     + s*8+tg+4]);
            uint32_t a3 = relu_tf32(sq[(g+8)*P2_RS + s*8+tg+4]);
            n0 += __uint_as_float(a0)*ksA[s] + __uint_as_float(a2)*ksB[s];
            n1 += __uint_as_float(a1)*ksA[s] + __uint_as_float(a3)*ksB[s];
            #pragma unroll
            for(int n=0;n<8;n++)
                mma_tf32(C[n], a0, a1, a2, a3, B0[n][s], B1[n][s]);
        }

        n0 += __shfl_xor_sync(0xffffffffu, n0, 1);
        n0 += __shfl_xor_sync(0xffffffffu, n0, 2);
        n1 += __shfl_xor_sync(0xffffffffu, n1, 1);
        n1 += __shfl_xor_sync(0xffffffffu, n1, 2);
        float i0 = 1.0f / fmaxf(n0, 1e-6f);
        float i1 = 1.0f / fmaxf(n1, 1e-6f);

        float* Or0 = O + (rowbase + (size_t)mt*16 + g)*DD;
        float* Or1 = Or0 + 8*DD;
        #pragma unroll
        for(int n=0;n<8;n++){
            float2 v0 = make_float2(C[n][0]*i0, C[n][1]*i0);
            float2 v1 = make_float2(C[n][2]*i1, C[n][3]*i1);
            *(float2*)(Or0 + n*8 + tg*2) = v0;
            *(float2*)(Or1 + n*8 + tg*2) = v1;
        }
        __syncwarp();
    }
    #undef P2_ISSUE
}

extern "C" void kernel_launch(void* const* d_in, const int* in_sizes, int n_in,
                              void* d_out, int out_size){
    const float* Q = (const float*)d_in[0];
    const float* K = (const float*)d_in[1];
    const float* V = (const float*)d_in[2];
    float* O = (float*)d_out;
    cudaFuncSetAttribute(pass1_kernel, cudaFuncAttributeMaxDynamicSharedMemorySize, P1_SMEM);
    cudaFuncSetAttribute(pass2_kernel, cudaFuncAttributeMaxDynamicSharedMemorySize, P2_SMEM);
    pass1_kernel<<<dim3(SPLIT/P1_WARPS, BH), 128, P1_SMEM>>>(K, V);
    reduce_kernel<<<BH, 256>>>();
    pass2_kernel<<<dim3(P2_PARTS, BH), 128, P2_SMEM>>>(Q, O);
}